// round 1
// baseline (speedup 1.0000x reference)
#include <cuda_runtime.h>
#include <math.h>

#define BATCH     16
#define MEM_DIM   172
#define TOK       4096
#define TIME_DIM  100
#define NCAT      22   // rows of cat_mem per batch (11 from W1, 11 from W2)
#define NTEX      21   // rows of texp per batch
#define LEN_TOK   512

// Scratch: intermediate projected rows (device globals — allocation-free).
__device__ float g_cat [BATCH * NCAT * TOK];   // 5.77 MB
__device__ float g_texp[BATCH * NTEX * TOK];   // 5.50 MB

// ---------------------------------------------------------------------------
// Kernel 1: cat_mem[b, half*11 + i, :] = memory[node] @ W{1,2} + b{1,2}
// grid: (32, 16)  block: 256.  blockIdx.x = b*2+half, blockIdx.y = column tile.
// ---------------------------------------------------------------------------
__global__ void k_memproj(const float* __restrict__ memory,
                          const int*   __restrict__ src_nodes,
                          const int*   __restrict__ dst_nodes,
                          const int*   __restrict__ src_nei,
                          const int*   __restrict__ dst_nei,
                          const float* __restrict__ W1, const float* __restrict__ b1,
                          const float* __restrict__ W2, const float* __restrict__ b2)
{
    const int half = blockIdx.x & 1;
    const int b    = blockIdx.x >> 1;
    const int col  = blockIdx.y * 256 + threadIdx.x;

    __shared__ float sm[11 * MEM_DIM];
    __shared__ int   nodes[11];

    if (threadIdx.x < 11) {
        int i = threadIdx.x;
        int n;
        if (half == 0) n = (i == 0) ? src_nodes[b] : dst_nei[b * 10 + i - 1];
        else           n = (i == 0) ? dst_nodes[b] : src_nei[b * 10 + i - 1];
        nodes[i] = n;
    }
    __syncthreads();

    for (int idx = threadIdx.x; idx < 11 * MEM_DIM; idx += 256) {
        int r = idx / MEM_DIM;
        int k = idx - r * MEM_DIM;
        sm[idx] = memory[(long long)nodes[r] * MEM_DIM + k];
    }
    __syncthreads();

    const float* W  = half ? W2 : W1;
    const float* bb = half ? b2 : b1;

    float acc[11];
#pragma unroll
    for (int i = 0; i < 11; i++) acc[i] = 0.f;

    for (int k = 0; k < MEM_DIM; k++) {
        float w = __ldg(&W[k * TOK + col]);
#pragma unroll
        for (int i = 0; i < 11; i++)
            acc[i] = fmaf(sm[i * MEM_DIM + k], w, acc[i]);
    }

    float bias = bb[col];
    float* out = g_cat + ((size_t)(b * NCAT + half * 11)) * TOK + col;
#pragma unroll
    for (int i = 0; i < 11; i++)
        out[(size_t)i * TOK] = acc[i] + bias;
}

// ---------------------------------------------------------------------------
// Kernel 2: texp[b, i, :] = cos(delta_i * w_time + phase) @ Wt + bt
// grid: (16, 16)  block: 256.
// ---------------------------------------------------------------------------
__global__ void k_timeproj(const float* __restrict__ timestamps,
                           const float* __restrict__ se,   // src_edge_times
                           const float* __restrict__ de,   // dst_edge_times
                           const float* __restrict__ Wt,
                           const float* __restrict__ bt,
                           const float* __restrict__ w_time,
                           const float* __restrict__ phase)
{
    const int b   = blockIdx.x;
    const int col = blockIdx.y * 256 + threadIdx.x;

    __shared__ float tenc[NTEX * TIME_DIM];   // 2100 floats

    const float t0 = timestamps[b];
    for (int idx = threadIdx.x; idx < NTEX * TIME_DIM; idx += 256) {
        int i = idx / TIME_DIM;
        int k = idx - i * TIME_DIM;
        float delta;
        if (i == 0)       delta = 0.f;
        else if (i < 11)  delta = t0 - se[b * 10 + i - 1];
        else              delta = t0 - de[b * 10 + i - 11];
        tenc[idx] = cosf(delta * w_time[k] + phase[k]);
    }
    __syncthreads();

    float acc[NTEX];
#pragma unroll
    for (int i = 0; i < NTEX; i++) acc[i] = 0.f;

    for (int k = 0; k < TIME_DIM; k++) {
        float w = __ldg(&Wt[k * TOK + col]);
#pragma unroll
        for (int i = 0; i < NTEX; i++)
            acc[i] = fmaf(tenc[i * TIME_DIM + k], w, acc[i]);
    }

    float bias = bt[col];
    float* out = g_texp + ((size_t)b * NTEX) * TOK + col;
#pragma unroll
    for (int i = 0; i < NTEX; i++)
        out[(size_t)i * TOK] = acc[i] + bias;
}

// ---------------------------------------------------------------------------
// Kernel 3: broadcast-scatter. Stage all 43 source rows (for one batch, one
// 256-column tile) in shared, then stream 3*512 output rows with STG.128.
// grid: (16, 16)  block: 64 threads, each owning 4 columns (float4).
// ---------------------------------------------------------------------------
__global__ void k_scatter(float* __restrict__ out)
{
    const int b    = blockIdx.x;
    const int tile = blockIdx.y;          // 16 tiles of 256 columns
    const int tid  = threadIdx.x;         // 64 threads * float4 = 256 cols

    __shared__ float4 cs [NCAT][64];
    __shared__ float4 tsh[NTEX][64];

    const float4* catv  = reinterpret_cast<const float4*>(g_cat);
    const float4* texpv = reinterpret_cast<const float4*>(g_texp);
    const int v_per_row = TOK / 4;        // 1024
    const int vcol      = tile * 64 + tid;

#pragma unroll
    for (int i = 0; i < NCAT; i++)
        cs[i][tid] = catv[(size_t)(b * NCAT + i) * v_per_row + vcol];
#pragma unroll
    for (int i = 0; i < NTEX; i++)
        tsh[i][tid] = texpv[(size_t)(b * NTEX + i) * v_per_row + vcol];
    __syncthreads();

    const size_t T = (size_t)BATCH * LEN_TOK * v_per_row;   // per-tensor float4s
    float4* outv    = reinterpret_cast<float4*>(out);
    float4* out_src = outv;
    float4* out_dst = outv + T;
    float4* out_tim = outv + 2 * T;

    size_t o = (size_t)(b * LEN_TOK) * v_per_row + vcol;

    for (int t = 0; t < LEN_TOK; t++, o += v_per_row) {
        int s, d, tm;
        if (t == 0)        { s = 0;  d = 11;    tm = 0;      }
        else if (t < 15)   { s = 0;  d = 0;     tm = 0;      }
        else if (t < 225)  { int j = (t - 15)  / 21; s = 0;  d = 12 + j; tm = 1 + j;  }
        else if (t < 239)  { s = 11; d = 11;    tm = 0;      }
        else if (t < 449)  { int j = (t - 239) / 21; s = 11; d = 1 + j;  tm = 11 + j; }
        else               { s = 0;  d = 11;    tm = 0;      }

        out_src[o] = cs[s][tid];
        out_dst[o] = cs[d][tid];
        out_tim[o] = tsh[tm][tid];
    }
}

// ---------------------------------------------------------------------------
extern "C" void kernel_launch(void* const* d_in, const int* in_sizes, int n_in,
                              void* d_out, int out_size)
{
    const float* memory      = (const float*)d_in[0];
    const int*   src_nodes   = (const int*)  d_in[1];
    const int*   dst_nodes   = (const int*)  d_in[2];
    const int*   src_nei     = (const int*)  d_in[3];
    const int*   dst_nei     = (const int*)  d_in[4];
    const float* timestamps  = (const float*)d_in[5];
    const float* se          = (const float*)d_in[6];
    const float* de          = (const float*)d_in[7];
    const float* W1          = (const float*)d_in[8];
    const float* b1          = (const float*)d_in[9];
    const float* W2          = (const float*)d_in[10];
    const float* b2          = (const float*)d_in[11];
    const float* Wt          = (const float*)d_in[12];
    const float* bt          = (const float*)d_in[13];
    const float* w_time      = (const float*)d_in[14];
    const float* phase       = (const float*)d_in[15];
    float* out = (float*)d_out;

    k_memproj <<<dim3(BATCH * 2, TOK / 256), 256>>>(memory, src_nodes, dst_nodes,
                                                    src_nei, dst_nei,
                                                    W1, b1, W2, b2);
    k_timeproj<<<dim3(BATCH,     TOK / 256), 256>>>(timestamps, se, de,
                                                    Wt, bt, w_time, phase);
    k_scatter <<<dim3(BATCH, 16), 64>>>(out);
}

// round 2
// speedup vs baseline: 1.3643x; 1.3643x over previous
#include <cuda_runtime.h>
#include <math.h>

#define BATCH     16
#define MEM_DIM   172
#define TOK       4096
#define TIME_DIM  100
#define LEN_TOK   512

typedef unsigned long long ull;

// Packed {W1, W2} weights: 172*4096 f32x2 pairs (5.6 MB scratch, device global).
__device__ ull g_Wpack[MEM_DIM * TOK];

__device__ __forceinline__ ull pack2(float lo, float hi) {
    ull d; asm("mov.b64 %0, {%1, %2};" : "=l"(d) : "f"(lo), "f"(hi)); return d;
}
__device__ __forceinline__ void unpack2(ull v, float& lo, float& hi) {
    asm("mov.b64 {%0, %1}, %2;" : "=f"(lo), "=f"(hi) : "l"(v));
}
// Blackwell packed fp32 pair FMA (PTX ISA 8.6, sm_100+).
__device__ __forceinline__ ull fma2(ull a, ull b, ull c) {
    ull d; asm("fma.rn.f32x2 %0, %1, %2, %3;" : "=l"(d) : "l"(a), "l"(b), "l"(c)); return d;
}

// ---------------------------------------------------------------------------
__global__ void k_pack(const float* __restrict__ W1, const float* __restrict__ W2)
{
    int i = blockIdx.x * 256 + threadIdx.x;
    if (i < MEM_DIM * TOK) g_Wpack[i] = pack2(W1[i], W2[i]);
}

// ---------------------------------------------------------------------------
// Fully fused kernel. grid (16 batches, 16 column-tiles of 256), block = 256.
// Phase 1: stage A (22x172, row-pair interleaved) + tenc (100x22) + idx table.
// Phase 2: mem projection with f32x2 FMA (pairs = rows (i, 11+i) vs {W1,W2}).
// Phase 3: time projection with f32x2 FMA (pairs = rows (2p,2p+1) vs {wt,wt}).
// Phase 4: scatter 3*512 output rows from the 43-row smem result, STG.128.
// ---------------------------------------------------------------------------
__global__ void __launch_bounds__(256)
k_fused(const float* __restrict__ memory,
        const int*   __restrict__ src_nodes,
        const int*   __restrict__ dst_nodes,
        const int*   __restrict__ src_nei,
        const int*   __restrict__ dst_nei,
        const float* __restrict__ timestamps,
        const float* __restrict__ se,
        const float* __restrict__ de,
        const float* __restrict__ b1,
        const float* __restrict__ b2,
        const float* __restrict__ Wt,
        const float* __restrict__ bt,
        const float* __restrict__ w_time,
        const float* __restrict__ phase,
        float*       __restrict__ out)
{
    extern __shared__ float sh[];
    float* Ash  = sh;                           // [172][22]  (15136 B)
    float* Ten  = Ash + MEM_DIM * 22;           // [100][22]  ( 8800 B)
    float* res  = Ten + TIME_DIM * 22;          // [44][256]  (45056 B, 16B-aligned)
    int*   idxs = (int*)(res + 44 * 256);       // [512]      ( 2048 B)

    const int b    = blockIdx.x;
    const int tile = blockIdx.y;
    const int tid  = threadIdx.x;
    const int col  = tile * 256 + tid;

    // ---------------- Phase 1: staging ----------------
    // A rows, interleaved so slot 2i = cat row i (W1 group), 2i+1 = cat row 11+i (W2 group)
    for (int i = tid; i < 22 * MEM_DIM; i += 256) {
        int r = i / MEM_DIM;
        int k = i - r * MEM_DIM;
        int node;
        if (r == 0)       node = src_nodes[b];
        else if (r < 11)  node = dst_nei[b * 10 + r - 1];
        else if (r == 11) node = dst_nodes[b];
        else              node = src_nei[b * 10 + r - 12];
        int slot = (r < 11) ? (2 * r) : (2 * (r - 11) + 1);
        Ash[k * 22 + slot] = memory[(size_t)node * MEM_DIM + k];
    }

    const float t0 = timestamps[b];
    for (int i = tid; i < TIME_DIM * 22; i += 256) {
        int k = i / 22;
        int r = i - k * 22;
        float v = 0.f;
        if (r < 21) {
            float delta;
            if (r == 0)      delta = 0.f;
            else if (r < 11) delta = t0 - se[b * 10 + r - 1];
            else             delta = t0 - de[b * 10 + r - 11];
            v = cosf(delta * w_time[k] + phase[k]);
        }
        Ten[i] = v;
    }

    for (int t = tid; t < LEN_TOK; t += 256) {
        int s, d, tm;
        if (t == 0)        { s = 0;  d = 11;    tm = 0;      }
        else if (t < 15)   { s = 0;  d = 0;     tm = 0;      }
        else if (t < 225)  { int j = (t - 15)  / 21; s = 0;  d = 12 + j; tm = 1 + j;  }
        else if (t < 239)  { s = 11; d = 11;    tm = 0;      }
        else if (t < 449)  { int j = (t - 239) / 21; s = 11; d = 1 + j;  tm = 11 + j; }
        else               { s = 0;  d = 11;    tm = 0;      }
        idxs[t] = s | (d << 8) | ((tm + 22) << 16);
    }
    __syncthreads();

    // ---------------- Phase 2: mem projection (f32x2) ----------------
    {
        ull acc[11];
        const ull bi = pack2(b1[col], b2[col]);
#pragma unroll
        for (int p = 0; p < 11; p++) acc[p] = bi;

#pragma unroll 4
        for (int k = 0; k < MEM_DIM; k++) {
            ull w = __ldg(&g_Wpack[(size_t)k * TOK + col]);       // {w1, w2}
            const ull* ar = (const ull*)(Ash + k * 22);           // 11 row-pairs
#pragma unroll
            for (int p = 0; p < 11; p++)
                acc[p] = fma2(ar[p], w, acc[p]);
        }
#pragma unroll
        for (int p = 0; p < 11; p++) {
            float lo, hi; unpack2(acc[p], lo, hi);
            res[p * 256 + tid]        = lo;   // cat row p     (mem1)
            res[(11 + p) * 256 + tid] = hi;   // cat row 11+p  (mem2)
        }
    }

    // ---------------- Phase 3: time projection (f32x2) ----------------
    {
        ull acc[11];
        const float btc = bt[col];
        const ull bi = pack2(btc, btc);
#pragma unroll
        for (int p = 0; p < 11; p++) acc[p] = bi;

#pragma unroll 4
        for (int k = 0; k < TIME_DIM; k++) {
            float wt = __ldg(&Wt[(size_t)k * TOK + col]);
            ull w = pack2(wt, wt);
            const ull* ar = (const ull*)(Ten + k * 22);           // 11 pairs (row 21 = pad 0)
#pragma unroll
            for (int p = 0; p < 11; p++)
                acc[p] = fma2(ar[p], w, acc[p]);
        }
#pragma unroll
        for (int p = 0; p < 11; p++) {
            float lo, hi; unpack2(acc[p], lo, hi);
            res[(22 + 2 * p) * 256 + tid] = lo;   // texp row 2p
            res[(23 + 2 * p) * 256 + tid] = hi;   // texp row 2p+1 (p=10 -> pad row 43)
        }
    }
    __syncthreads();

    // ---------------- Phase 4: scatter ----------------
    const int lane = tid & 63;        // float4 column within tile
    const int grp  = tid >> 6;        // 4 token groups of 128
    const float4* resv = (const float4*)res;                   // [44][64]
    float4* outv = (float4*)out;
    const size_t T = (size_t)BATCH * LEN_TOK * (TOK / 4);      // per-tensor float4 count
    const size_t obase = (size_t)(b * LEN_TOK) * (TOK / 4) + tile * 64 + lane;

    const int tend = grp * 128 + 128;
    for (int t = grp * 128; t < tend; t++) {
        int e = idxs[t];
        float4 vs = resv[(e & 255)         * 64 + lane];
        float4 vd = resv[((e >> 8) & 255)  * 64 + lane];
        float4 vt = resv[(e >> 16)         * 64 + lane];
        size_t o = obase + (size_t)t * (TOK / 4);
        outv[o]         = vs;
        outv[o + T]     = vd;
        outv[o + 2 * T] = vt;
    }
}

// ---------------------------------------------------------------------------
extern "C" void kernel_launch(void* const* d_in, const int* in_sizes, int n_in,
                              void* d_out, int out_size)
{
    const float* memory      = (const float*)d_in[0];
    const int*   src_nodes   = (const int*)  d_in[1];
    const int*   dst_nodes   = (const int*)  d_in[2];
    const int*   src_nei     = (const int*)  d_in[3];
    const int*   dst_nei     = (const int*)  d_in[4];
    const float* timestamps  = (const float*)d_in[5];
    const float* se          = (const float*)d_in[6];
    const float* de          = (const float*)d_in[7];
    const float* W1          = (const float*)d_in[8];
    const float* b1          = (const float*)d_in[9];
    const float* W2          = (const float*)d_in[10];
    const float* b2          = (const float*)d_in[11];
    const float* Wt          = (const float*)d_in[12];
    const float* bt          = (const float*)d_in[13];
    const float* w_time      = (const float*)d_in[14];
    const float* phase       = (const float*)d_in[15];
    float* out = (float*)d_out;

    const int smem = (MEM_DIM * 22 + TIME_DIM * 22 + 44 * 256) * 4 + LEN_TOK * 4; // 71040 B
    cudaFuncSetAttribute(k_fused, cudaFuncAttributeMaxDynamicSharedMemorySize, smem);

    k_pack <<<(MEM_DIM * TOK + 255) / 256, 256>>>(W1, W2);
    k_fused<<<dim3(BATCH, TOK / 256), 256, smem>>>(memory, src_nodes, dst_nodes,
                                                   src_nei, dst_nei,
                                                   timestamps, se, de,
                                                   b1, b2, Wt, bt, w_time, phase,
                                                   out);
}

// round 3
// speedup vs baseline: 1.3886x; 1.0178x over previous
#include <cuda_runtime.h>
#include <math.h>

#define BATCH     16
#define MEM_DIM   172
#define TOK       4096
#define TIME_DIM  100
#define LEN_TOK   512
#define NROWS     44        // 22 cat rows + 21 texp rows + 1 pad

typedef unsigned long long ull;

// Projected rows scratch: [batch][44 rows][4096 cols] f32 = 11.5 MB (L2-resident).
__device__ float g_res[BATCH * NROWS * TOK];

__device__ __forceinline__ ull pack2(float lo, float hi) {
    ull d; asm("mov.b64 %0, {%1, %2};" : "=l"(d) : "f"(lo), "f"(hi)); return d;
}
__device__ __forceinline__ void unpack2(ull v, float& lo, float& hi) {
    asm("mov.b64 {%0, %1}, %2;" : "=f"(lo), "=f"(hi) : "l"(v));
}
// Blackwell packed fp32 pair FMA.
__device__ __forceinline__ ull fma2(ull a, ull b, ull c) {
    ull d; asm("fma.rn.f32x2 %0, %1, %2, %3;" : "=l"(d) : "l"(a), "l"(b), "l"(c)); return d;
}

// ---------------------------------------------------------------------------
// Kernel A: projections. grid (16 batches, 16 col-tiles of 256), block 256.
// Writes g_res rows: 0..21 = cat_mem, 22..42 = texp (43 = pad).
// ---------------------------------------------------------------------------
__global__ void __launch_bounds__(256)
k_proj(const float* __restrict__ memory,
       const int*   __restrict__ src_nodes,
       const int*   __restrict__ dst_nodes,
       const int*   __restrict__ src_nei,
       const int*   __restrict__ dst_nei,
       const float* __restrict__ timestamps,
       const float* __restrict__ se,
       const float* __restrict__ de,
       const float* __restrict__ W1, const float* __restrict__ b1,
       const float* __restrict__ W2, const float* __restrict__ b2,
       const float* __restrict__ Wt, const float* __restrict__ bt,
       const float* __restrict__ w_time,
       const float* __restrict__ phase)
{
    __shared__ float Ash[MEM_DIM * 22];     // [k][slot], slot 2i = row i, 2i+1 = row 11+i
    __shared__ float Ten[TIME_DIM * 22];    // [k][row], row 21 = pad 0

    const int b    = blockIdx.x;
    const int tile = blockIdx.y;
    const int tid  = threadIdx.x;
    const int col  = tile * 256 + tid;

    // --- staging ---
    for (int i = tid; i < 22 * MEM_DIM; i += 256) {
        int r = i / MEM_DIM;
        int k = i - r * MEM_DIM;
        int node;
        if (r == 0)       node = src_nodes[b];
        else if (r < 11)  node = dst_nei[b * 10 + r - 1];
        else if (r == 11) node = dst_nodes[b];
        else              node = src_nei[b * 10 + r - 12];
        int slot = (r < 11) ? (2 * r) : (2 * (r - 11) + 1);
        Ash[k * 22 + slot] = memory[(size_t)node * MEM_DIM + k];
    }

    const float t0 = timestamps[b];
    for (int i = tid; i < TIME_DIM * 22; i += 256) {
        int k = i / 22;
        int r = i - k * 22;
        float v = 0.f;
        if (r < 21) {
            float delta;
            if (r == 0)      delta = 0.f;
            else if (r < 11) delta = t0 - se[b * 10 + r - 1];
            else             delta = t0 - de[b * 10 + r - 11];
            v = cosf(delta * w_time[k] + phase[k]);
        }
        Ten[i] = v;
    }
    __syncthreads();

    float* resb = g_res + (size_t)b * NROWS * TOK + col;

    // --- mem projection: rows (p, 11+p) paired against {W1, W2} ---
    {
        ull acc[11];
        const ull bi = pack2(b1[col], b2[col]);
#pragma unroll
        for (int p = 0; p < 11; p++) acc[p] = bi;

#pragma unroll 4
        for (int k = 0; k < MEM_DIM; k++) {
            ull w = pack2(__ldg(&W1[(size_t)k * TOK + col]),
                          __ldg(&W2[(size_t)k * TOK + col]));
            const ull* ar = (const ull*)(Ash + k * 22);
#pragma unroll
            for (int p = 0; p < 11; p++)
                acc[p] = fma2(ar[p], w, acc[p]);
        }
#pragma unroll
        for (int p = 0; p < 11; p++) {
            float lo, hi; unpack2(acc[p], lo, hi);
            resb[(size_t)p * TOK]        = lo;
            resb[(size_t)(11 + p) * TOK] = hi;
        }
    }

    // --- time projection: texp rows (2p, 2p+1) paired against {wt, wt} ---
    {
        ull acc[11];
        const float btc = bt[col];
        const ull bi = pack2(btc, btc);
#pragma unroll
        for (int p = 0; p < 11; p++) acc[p] = bi;

#pragma unroll 4
        for (int k = 0; k < TIME_DIM; k++) {
            float wt = __ldg(&Wt[(size_t)k * TOK + col]);
            ull w = pack2(wt, wt);
            const ull* ar = (const ull*)(Ten + k * 22);
#pragma unroll
            for (int p = 0; p < 11; p++)
                acc[p] = fma2(ar[p], w, acc[p]);
        }
#pragma unroll
        for (int p = 0; p < 11; p++) {
            float lo, hi; unpack2(acc[p], lo, hi);
            resb[(size_t)(22 + 2 * p) * TOK] = lo;
            resb[(size_t)(23 + 2 * p) * TOK] = hi;   // p=10 -> pad row 43
        }
    }
}

// ---------------------------------------------------------------------------
// Kernel B: scatter. grid (16 batches, 16 col-tiles, 8 token-slices) = 2048 CTAs.
// block 256 = 64 float4 lanes x 4 token groups of 16.
// ---------------------------------------------------------------------------
__global__ void __launch_bounds__(256)
k_scat(float* __restrict__ out)
{
    __shared__ float4 sres[NROWS * 64];     // 45056 B

    const int b     = blockIdx.x;
    const int tile  = blockIdx.y;
    const int slice = blockIdx.z;
    const int tid   = threadIdx.x;
    const int lane  = tid & 63;
    const int grp   = tid >> 6;

    const float4* gresv = (const float4*)g_res;
    const int vrow = TOK / 4;               // 1024

    // stage 44 rows x 64 float4 for this (b, tile)
#pragma unroll
    for (int i = tid; i < NROWS * 64; i += 256)
        sres[i] = gresv[(size_t)(b * NROWS + (i >> 6)) * vrow + tile * 64 + (i & 63)];
    __syncthreads();

    float4* outv = (float4*)out;
    const size_t T = (size_t)BATCH * LEN_TOK * vrow;     // per-tensor float4s
    const size_t obase = (size_t)(b * LEN_TOK) * vrow + tile * 64 + lane;
    const int t0 = slice * 64 + grp * 16;

#pragma unroll 4
    for (int it = 0; it < 16; it++) {
        const int t = t0 + it;
        int s, d, tm;
        if (t == 0)        { s = 0;  d = 11;    tm = 0;      }
        else if (t < 15)   { s = 0;  d = 0;     tm = 0;      }
        else if (t < 225)  { int j = (t - 15)  / 21; s = 0;  d = 12 + j; tm = 1 + j;  }
        else if (t < 239)  { s = 11; d = 11;    tm = 0;      }
        else if (t < 449)  { int j = (t - 239) / 21; s = 11; d = 1 + j;  tm = 11 + j; }
        else               { s = 0;  d = 11;    tm = 0;      }

        float4 vs = sres[s * 64 + lane];
        float4 vd = sres[d * 64 + lane];
        float4 vt = sres[(22 + tm) * 64 + lane];
        const size_t o = obase + (size_t)t * vrow;
        outv[o]         = vs;
        outv[o + T]     = vd;
        outv[o + 2 * T] = vt;
    }
}

// ---------------------------------------------------------------------------
extern "C" void kernel_launch(void* const* d_in, const int* in_sizes, int n_in,
                              void* d_out, int out_size)
{
    const float* memory      = (const float*)d_in[0];
    const int*   src_nodes   = (const int*)  d_in[1];
    const int*   dst_nodes   = (const int*)  d_in[2];
    const int*   src_nei     = (const int*)  d_in[3];
    const int*   dst_nei     = (const int*)  d_in[4];
    const float* timestamps  = (const float*)d_in[5];
    const float* se          = (const float*)d_in[6];
    const float* de          = (const float*)d_in[7];
    const float* W1          = (const float*)d_in[8];
    const float* b1          = (const float*)d_in[9];
    const float* W2          = (const float*)d_in[10];
    const float* b2          = (const float*)d_in[11];
    const float* Wt          = (const float*)d_in[12];
    const float* bt          = (const float*)d_in[13];
    const float* w_time      = (const float*)d_in[14];
    const float* phase       = (const float*)d_in[15];
    float* out = (float*)d_out;

    k_proj<<<dim3(BATCH, TOK / 256), 256>>>(memory, src_nodes, dst_nodes,
                                            src_nei, dst_nei,
                                            timestamps, se, de,
                                            W1, b1, W2, b2, Wt, bt,
                                            w_time, phase);
    k_scat<<<dim3(BATCH, TOK / 256, 8), 256>>>(out);
}

// round 4
// speedup vs baseline: 1.3934x; 1.0035x over previous
#include <cuda_runtime.h>
#include <math.h>

#define BATCH     16
#define MEM_DIM   172
#define TOK       4096
#define TIME_DIM  100
#define LEN_TOK   512
#define NROWS     44        // 22 cat + 21 texp + 1 pad

typedef unsigned long long ull;

// Projected rows scratch: [batch][44][4096] f32 = 11.5 MB (L2-resident).
__device__ float g_res[BATCH * NROWS * TOK];

__device__ __forceinline__ ull pack2(float lo, float hi) {
    ull d; asm("mov.b64 %0, {%1, %2};" : "=l"(d) : "f"(lo), "f"(hi)); return d;
}
__device__ __forceinline__ void unpack2(ull v, float& lo, float& hi) {
    asm("mov.b64 {%0, %1}, %2;" : "=f"(lo), "=f"(hi) : "l"(v));
}
__device__ __forceinline__ ull fma2(ull a, ull b, ull c) {
    ull d; asm("fma.rn.f32x2 %0, %1, %2, %3;" : "=l"(d) : "l"(a), "l"(b), "l"(c)); return d;
}
__device__ __forceinline__ ull add2(ull a, ull b) {
    ull d; asm("add.rn.f32x2 %0, %1, %2;" : "=l"(d) : "l"(a), "l"(b)); return d;
}

// ---------------------------------------------------------------------------
// Kernel A: projections, 4-way k-split.
// grid (16 batches, 32 col-tiles of 128), block 512 = 128 cols x 4 k-slices.
// g_res rows: 0..21 = cat_mem, 22..42 = texp, 43 = pad.
// ---------------------------------------------------------------------------
#define ASTRIDE 24      // padded row stride (16B aligned)
#define RED_N   (3 * 128 * 11)

__global__ void __launch_bounds__(512)
k_proj(const float* __restrict__ memory,
       const int*   __restrict__ src_nodes,
       const int*   __restrict__ dst_nodes,
       const int*   __restrict__ src_nei,
       const int*   __restrict__ dst_nei,
       const float* __restrict__ timestamps,
       const float* __restrict__ se,
       const float* __restrict__ de,
       const float* __restrict__ W1, const float* __restrict__ b1,
       const float* __restrict__ W2, const float* __restrict__ b2,
       const float* __restrict__ Wt, const float* __restrict__ bt,
       const float* __restrict__ w_time,
       const float* __restrict__ phase)
{
    extern __shared__ float sh[];
    float* Ash = sh;                              // [172][24]  slot 2i=row i, 2i+1=row 11+i
    float* Ten = Ash + MEM_DIM * ASTRIDE;         // [100][24]  rows 0..20 real, 21 pad
    ull*   red = (ull*)(Ten + TIME_DIM * ASTRIDE);// [3][128][11]

    const int b     = blockIdx.x;
    const int tile  = blockIdx.y;
    const int tid   = threadIdx.x;
    const int cl    = tid & 127;
    const int slice = tid >> 7;
    const int col   = tile * 128 + cl;

    // ---- staging ----
    for (int i = tid; i < 22 * MEM_DIM; i += 512) {
        int r = i / MEM_DIM;
        int k = i - r * MEM_DIM;
        int node;
        if (r == 0)       node = src_nodes[b];
        else if (r < 11)  node = dst_nei[b * 10 + r - 1];
        else if (r == 11) node = dst_nodes[b];
        else              node = src_nei[b * 10 + r - 12];
        int slot = (r < 11) ? (2 * r) : (2 * (r - 11) + 1);
        Ash[k * ASTRIDE + slot] = memory[(size_t)node * MEM_DIM + k];
    }
    const float t0 = timestamps[b];
    for (int i = tid; i < TIME_DIM * 22; i += 512) {
        int k = i / 22;
        int r = i - k * 22;
        float v = 0.f;
        if (r < 21) {
            float delta;
            if (r == 0)      delta = 0.f;
            else if (r < 11) delta = t0 - se[b * 10 + r - 1];
            else             delta = t0 - de[b * 10 + r - 11];
            v = cosf(delta * w_time[k] + phase[k]);
        }
        Ten[k * ASTRIDE + r] = v;
    }
    __syncthreads();

    float* resb = g_res + (size_t)b * NROWS * TOK + col;

    // ---- mem projection: pairs (row p, row 11+p) vs {W1, W2} ----
    {
        ull acc[11];
        const ull bi = pack2(b1[col], b2[col]);
#pragma unroll
        for (int p = 0; p < 11; p++) acc[p] = slice == 0 ? bi : 0ull;

        const int k0 = slice * 43, k1 = k0 + 43;
#pragma unroll 2
        for (int k = k0; k < k1; k++) {
            ull w = pack2(__ldg(&W1[(size_t)k * TOK + col]),
                          __ldg(&W2[(size_t)k * TOK + col]));
            const float* a = Ash + k * ASTRIDE;
#pragma unroll
            for (int q = 0; q < 5; q++) {
                ulonglong2 v = *(const ulonglong2*)(a + 4 * q);
                acc[2 * q]     = fma2(v.x, w, acc[2 * q]);
                acc[2 * q + 1] = fma2(v.y, w, acc[2 * q + 1]);
            }
            acc[10] = fma2(*(const ull*)(a + 20), w, acc[10]);
        }

        if (slice) {
#pragma unroll
            for (int p = 0; p < 11; p++)
                red[((slice - 1) * 128 + cl) * 11 + p] = acc[p];
        }
        __syncthreads();
        if (slice == 0) {
#pragma unroll
            for (int s = 0; s < 3; s++)
#pragma unroll
                for (int p = 0; p < 11; p++)
                    acc[p] = add2(acc[p], red[(s * 128 + cl) * 11 + p]);
#pragma unroll
            for (int p = 0; p < 11; p++) {
                float lo, hi; unpack2(acc[p], lo, hi);
                resb[(size_t)p * TOK]        = lo;
                resb[(size_t)(11 + p) * TOK] = hi;
            }
        }
        __syncthreads();   // red reused below
    }

    // ---- time projection: pairs (row 2p, row 2p+1) vs {wt, wt} ----
    {
        ull acc[11];
        const float btc = bt[col];
        const ull bi = pack2(btc, btc);
#pragma unroll
        for (int p = 0; p < 11; p++) acc[p] = slice == 0 ? bi : 0ull;

        const int k0 = slice * 25, k1 = k0 + 25;
#pragma unroll 2
        for (int k = k0; k < k1; k++) {
            float wt = __ldg(&Wt[(size_t)k * TOK + col]);
            ull w = pack2(wt, wt);
            const float* a = Ten + k * ASTRIDE;
#pragma unroll
            for (int q = 0; q < 5; q++) {
                ulonglong2 v = *(const ulonglong2*)(a + 4 * q);
                acc[2 * q]     = fma2(v.x, w, acc[2 * q]);
                acc[2 * q + 1] = fma2(v.y, w, acc[2 * q + 1]);
            }
            acc[10] = fma2(*(const ull*)(a + 20), w, acc[10]);
        }

        if (slice) {
#pragma unroll
            for (int p = 0; p < 11; p++)
                red[((slice - 1) * 128 + cl) * 11 + p] = acc[p];
        }
        __syncthreads();
        if (slice == 0) {
#pragma unroll
            for (int s = 0; s < 3; s++)
#pragma unroll
                for (int p = 0; p < 11; p++)
                    acc[p] = add2(acc[p], red[(s * 128 + cl) * 11 + p]);
#pragma unroll
            for (int p = 0; p < 11; p++) {
                float lo, hi; unpack2(acc[p], lo, hi);
                resb[(size_t)(22 + 2 * p) * TOK] = lo;
                resb[(size_t)(23 + 2 * p) * TOK] = hi;   // p=10 -> pad row 43
            }
        }
    }
}

// ---------------------------------------------------------------------------
// Kernel B: scatter. grid (16, 16, 4) = 1024 CTAs, block 512.
// block = 64 float4-lanes x 8 token-groups of 16 tokens (128 tokens/CTA).
// ---------------------------------------------------------------------------
__global__ void __launch_bounds__(512)
k_scat(float* __restrict__ out)
{
    __shared__ float4 sres[NROWS * 64];     // 45056 B

    const int b    = blockIdx.x;
    const int tile = blockIdx.y;
    const int seg  = blockIdx.z;
    const int tid  = threadIdx.x;
    const int lane = tid & 63;
    const int grp  = tid >> 6;

    const float4* gresv = (const float4*)g_res;
    const int vrow = TOK / 4;               // 1024

#pragma unroll
    for (int i = tid; i < NROWS * 64; i += 512)
        sres[i] = gresv[(size_t)(b * NROWS + (i >> 6)) * vrow + tile * 64 + (i & 63)];
    __syncthreads();

    float4* outv = (float4*)out;
    const size_t T = (size_t)BATCH * LEN_TOK * vrow;
    const size_t obase = (size_t)(b * LEN_TOK) * vrow + tile * 64 + lane;
    const int t0 = seg * 128 + grp * 16;

#pragma unroll 4
    for (int it = 0; it < 16; it++) {
        const int t = t0 + it;
        int s, d, tm;
        if (t == 0)        { s = 0;  d = 11;    tm = 0;      }
        else if (t < 15)   { s = 0;  d = 0;     tm = 0;      }
        else if (t < 225)  { int j = (t - 15)  / 21; s = 0;  d = 12 + j; tm = 1 + j;  }
        else if (t < 239)  { s = 11; d = 11;    tm = 0;      }
        else if (t < 449)  { int j = (t - 239) / 21; s = 11; d = 1 + j;  tm = 11 + j; }
        else               { s = 0;  d = 11;    tm = 0;      }

        float4 vs = sres[s * 64 + lane];
        float4 vd = sres[d * 64 + lane];
        float4 vt = sres[(22 + tm) * 64 + lane];
        const size_t o = obase + (size_t)t * vrow;
        outv[o]         = vs;
        outv[o + T]     = vd;
        outv[o + 2 * T] = vt;
    }
}

// ---------------------------------------------------------------------------
extern "C" void kernel_launch(void* const* d_in, const int* in_sizes, int n_in,
                              void* d_out, int out_size)
{
    const float* memory      = (const float*)d_in[0];
    const int*   src_nodes   = (const int*)  d_in[1];
    const int*   dst_nodes   = (const int*)  d_in[2];
    const int*   src_nei     = (const int*)  d_in[3];
    const int*   dst_nei     = (const int*)  d_in[4];
    const float* timestamps  = (const float*)d_in[5];
    const float* se          = (const float*)d_in[6];
    const float* de          = (const float*)d_in[7];
    const float* W1          = (const float*)d_in[8];
    const float* b1          = (const float*)d_in[9];
    const float* W2          = (const float*)d_in[10];
    const float* b2          = (const float*)d_in[11];
    const float* Wt          = (const float*)d_in[12];
    const float* bt          = (const float*)d_in[13];
    const float* w_time      = (const float*)d_in[14];
    const float* phase       = (const float*)d_in[15];
    float* out = (float*)d_out;

    const int smem = (MEM_DIM * ASTRIDE + TIME_DIM * ASTRIDE) * 4 + RED_N * 8; // 59904 B
    static int configured = 0;
    cudaFuncSetAttribute(k_proj, cudaFuncAttributeMaxDynamicSharedMemorySize, smem);
    (void)configured;

    k_proj<<<dim3(BATCH, TOK / 128), 512, smem>>>(memory, src_nodes, dst_nodes,
                                                  src_nei, dst_nei,
                                                  timestamps, se, de,
                                                  W1, b1, W2, b2, Wt, bt,
                                                  w_time, phase);
    k_scat<<<dim3(BATCH, TOK / 256, 4), 512>>>(out);
}

// round 5
// speedup vs baseline: 1.5662x; 1.1240x over previous
#include <cuda_runtime.h>
#include <math.h>

#define BATCH     16
#define MEM_DIM   172
#define TOK       4096
#define TIME_DIM  100
#define LEN_TOK   512
#define NROWS     44        // 22 cat + 21 texp + 1 pad
#define ASTRIDE   24        // padded smem row stride (16B aligned)

typedef unsigned long long ull;

// Projected rows scratch: [batch][44][4096] f32 = 11.5 MB (L2-resident).
__device__ float g_res[BATCH * NROWS * TOK];

__device__ __forceinline__ ull pack2(float lo, float hi) {
    ull d; asm("mov.b64 %0, {%1, %2};" : "=l"(d) : "f"(lo), "f"(hi)); return d;
}
__device__ __forceinline__ void unpack2(ull v, float& lo, float& hi) {
    asm("mov.b64 {%0, %1}, %2;" : "=f"(lo), "=f"(hi) : "l"(v));
}
__device__ __forceinline__ ull fma2(ull a, ull b, ull c) {
    ull d; asm("fma.rn.f32x2 %0, %1, %2, %3;" : "=l"(d) : "l"(a), "l"(b), "l"(c)); return d;
}
__device__ __forceinline__ ull add2(ull a, ull b) {
    ull d; asm("add.rn.f32x2 %0, %1, %2;" : "=l"(d) : "l"(a), "l"(b)); return d;
}

// ---------------------------------------------------------------------------
// Kernel A: projections. grid (16 b, 32 tiles of 128 cols), block 256
// (= 128 cols x 2 k-slices). Explicit depth-4 register prefetch of W.
// g_res rows: 0..21 = cat_mem, 22..42 = texp, 43 = pad.
// ---------------------------------------------------------------------------
__global__ void __launch_bounds__(256)
k_proj(const float* __restrict__ memory,
       const int*   __restrict__ src_nodes,
       const int*   __restrict__ dst_nodes,
       const int*   __restrict__ src_nei,
       const int*   __restrict__ dst_nei,
       const float* __restrict__ timestamps,
       const float* __restrict__ se,
       const float* __restrict__ de,
       const float* __restrict__ W1, const float* __restrict__ b1,
       const float* __restrict__ W2, const float* __restrict__ b2,
       const float* __restrict__ Wt, const float* __restrict__ bt,
       const float* __restrict__ w_time,
       const float* __restrict__ phase)
{
    __shared__ float Ash[MEM_DIM * ASTRIDE];    // [k][slot]: 2i=row i, 2i+1=row 11+i
    __shared__ float Ten[TIME_DIM * ASTRIDE];   // [k][row], row 21 = pad 0
    __shared__ ull   red[128 * 11];             // cross-slice partials

    const int b     = blockIdx.x;
    const int tile  = blockIdx.y;
    const int tid   = threadIdx.x;
    const int cl    = tid & 127;
    const int slice = tid >> 7;                 // 0 or 1
    const int col   = tile * 128 + cl;

    // ---- staging ----
    for (int i = tid; i < 22 * MEM_DIM; i += 256) {
        int r = i / MEM_DIM;
        int k = i - r * MEM_DIM;
        int node;
        if (r == 0)       node = src_nodes[b];
        else if (r < 11)  node = dst_nei[b * 10 + r - 1];
        else if (r == 11) node = dst_nodes[b];
        else              node = src_nei[b * 10 + r - 12];
        int slot = (r < 11) ? (2 * r) : (2 * (r - 11) + 1);
        Ash[k * ASTRIDE + slot] = memory[(size_t)node * MEM_DIM + k];
    }
    const float t0 = timestamps[b];
    for (int i = tid; i < TIME_DIM * 22; i += 256) {
        int k = i / 22;
        int r = i - k * 22;
        float v = 0.f;
        if (r < 21) {
            float delta;
            if (r == 0)      delta = 0.f;
            else if (r < 11) delta = t0 - se[b * 10 + r - 1];
            else             delta = t0 - de[b * 10 + r - 11];
            v = cosf(delta * w_time[k] + phase[k]);
        }
        Ten[k * ASTRIDE + r] = v;
    }
    __syncthreads();

    float* resb = g_res + (size_t)b * NROWS * TOK + col;

    // ---- mem projection: pairs (row p, row 11+p) vs {W1, W2} ----
    {
        ull acc[11];
        const ull bi = pack2(b1[col], b2[col]);
#pragma unroll
        for (int p = 0; p < 11; p++) acc[p] = slice == 0 ? bi : 0ull;

        // k-split: slice0 -> [0,84), slice1 -> [84,172). Both multiples of 4.
        const int k0 = slice ? 84 : 0;
        const int k1 = slice ? 172 : 84;

        float w1b[4], w2b[4];
#pragma unroll
        for (int i = 0; i < 4; i++) {
            w1b[i] = W1[(size_t)(k0 + i) * TOK + col];
            w2b[i] = W2[(size_t)(k0 + i) * TOK + col];
        }

#pragma unroll 4
        for (int k = k0; k < k1; k++) {
            const int s = (k - k0) & 3;
            ull w = pack2(w1b[s], w2b[s]);
            int kp = k + 4; if (kp >= k1) kp = k1 - 1;   // clamped prefetch
            w1b[s] = W1[(size_t)kp * TOK + col];
            w2b[s] = W2[(size_t)kp * TOK + col];

            const float* a = Ash + k * ASTRIDE;
#pragma unroll
            for (int q = 0; q < 5; q++) {
                ulonglong2 v = *(const ulonglong2*)(a + 4 * q);
                acc[2 * q]     = fma2(v.x, w, acc[2 * q]);
                acc[2 * q + 1] = fma2(v.y, w, acc[2 * q + 1]);
            }
            acc[10] = fma2(*(const ull*)(a + 20), w, acc[10]);
        }

        if (slice) {
#pragma unroll
            for (int p = 0; p < 11; p++) red[cl * 11 + p] = acc[p];
        }
        __syncthreads();
        if (slice == 0) {
#pragma unroll
            for (int p = 0; p < 11; p++) {
                acc[p] = add2(acc[p], red[cl * 11 + p]);
                float lo, hi; unpack2(acc[p], lo, hi);
                resb[(size_t)p * TOK]        = lo;
                resb[(size_t)(11 + p) * TOK] = hi;
            }
        }
        __syncthreads();   // red reused below
    }

    // ---- time projection: pairs (row 2p, row 2p+1) vs {wt, wt} ----
    {
        ull acc[11];
        const float btc = bt[col];
        const ull bi = pack2(btc, btc);
#pragma unroll
        for (int p = 0; p < 11; p++) acc[p] = slice == 0 ? bi : 0ull;

        // k-split: slice0 -> [0,48), slice1 -> [48,100). Both multiples of 4.
        const int k0 = slice ? 48 : 0;
        const int k1 = slice ? 100 : 48;

        float wtb[4];
#pragma unroll
        for (int i = 0; i < 4; i++)
            wtb[i] = Wt[(size_t)(k0 + i) * TOK + col];

#pragma unroll 4
        for (int k = k0; k < k1; k++) {
            const int s = (k - k0) & 3;
            ull w = pack2(wtb[s], wtb[s]);
            int kp = k + 4; if (kp >= k1) kp = k1 - 1;
            wtb[s] = Wt[(size_t)kp * TOK + col];

            const float* a = Ten + k * ASTRIDE;
#pragma unroll
            for (int q = 0; q < 5; q++) {
                ulonglong2 v = *(const ulonglong2*)(a + 4 * q);
                acc[2 * q]     = fma2(v.x, w, acc[2 * q]);
                acc[2 * q + 1] = fma2(v.y, w, acc[2 * q + 1]);
            }
            acc[10] = fma2(*(const ull*)(a + 20), w, acc[10]);
        }

        if (slice) {
#pragma unroll
            for (int p = 0; p < 11; p++) red[cl * 11 + p] = acc[p];
        }
        __syncthreads();
        if (slice == 0) {
#pragma unroll
            for (int p = 0; p < 11; p++) {
                acc[p] = add2(acc[p], red[cl * 11 + p]);
                float lo, hi; unpack2(acc[p], lo, hi);
                resb[(size_t)(22 + 2 * p) * TOK] = lo;
                resb[(size_t)(23 + 2 * p) * TOK] = hi;   // p=10 -> pad row 43
            }
        }
    }
}

// ---------------------------------------------------------------------------
// Kernel B: scatter (round-3 shape). grid (16,16,8)=2048 CTAs, block 256
// = 64 float4-lanes x 4 token-groups of 16. Streaming stores.
// ---------------------------------------------------------------------------
__global__ void __launch_bounds__(256)
k_scat(float* __restrict__ out)
{
    __shared__ float4 sres[NROWS * 64];     // 45056 B

    const int b     = blockIdx.x;
    const int tile  = blockIdx.y;
    const int slice = blockIdx.z;
    const int tid   = threadIdx.x;
    const int lane  = tid & 63;
    const int grp   = tid >> 6;

    const float4* gresv = (const float4*)g_res;
    const int vrow = TOK / 4;               // 1024

#pragma unroll
    for (int i = tid; i < NROWS * 64; i += 256)
        sres[i] = gresv[(size_t)(b * NROWS + (i >> 6)) * vrow + tile * 64 + (i & 63)];
    __syncthreads();

    float4* outv = (float4*)out;
    const size_t T = (size_t)BATCH * LEN_TOK * vrow;
    const size_t obase = (size_t)(b * LEN_TOK) * vrow + tile * 64 + lane;
    const int t0 = slice * 64 + grp * 16;

#pragma unroll 4
    for (int it = 0; it < 16; it++) {
        const int t = t0 + it;
        int s, d, tm;
        if (t == 0)        { s = 0;  d = 11;    tm = 0;      }
        else if (t < 15)   { s = 0;  d = 0;     tm = 0;      }
        else if (t < 225)  { int j = (t - 15)  / 21; s = 0;  d = 12 + j; tm = 1 + j;  }
        else if (t < 239)  { s = 11; d = 11;    tm = 0;      }
        else if (t < 449)  { int j = (t - 239) / 21; s = 11; d = 1 + j;  tm = 11 + j; }
        else               { s = 0;  d = 11;    tm = 0;      }

        float4 vs = sres[s * 64 + lane];
        float4 vd = sres[d * 64 + lane];
        float4 vt = sres[(22 + tm) * 64 + lane];
        const size_t o = obase + (size_t)t * vrow;
        __stcs(&outv[o],         vs);
        __stcs(&outv[o + T],     vd);
        __stcs(&outv[o + 2 * T], vt);
    }
}

// ---------------------------------------------------------------------------
extern "C" void kernel_launch(void* const* d_in, const int* in_sizes, int n_in,
                              void* d_out, int out_size)
{
    const float* memory      = (const float*)d_in[0];
    const int*   src_nodes   = (const int*)  d_in[1];
    const int*   dst_nodes   = (const int*)  d_in[2];
    const int*   src_nei     = (const int*)  d_in[3];
    const int*   dst_nei     = (const int*)  d_in[4];
    const float* timestamps  = (const float*)d_in[5];
    const float* se          = (const float*)d_in[6];
    const float* de          = (const float*)d_in[7];
    const float* W1          = (const float*)d_in[8];
    const float* b1          = (const float*)d_in[9];
    const float* W2          = (const float*)d_in[10];
    const float* b2          = (const float*)d_in[11];
    const float* Wt          = (const float*)d_in[12];
    const float* bt          = (const float*)d_in[13];
    const float* w_time      = (const float*)d_in[14];
    const float* phase       = (const float*)d_in[15];
    float* out = (float*)d_out;

    k_proj<<<dim3(BATCH, TOK / 128), 256>>>(memory, src_nodes, dst_nodes,
                                            src_nei, dst_nei,
                                            timestamps, se, de,
                                            W1, b1, W2, b2, Wt, bt,
                                            w_time, phase);
    k_scat<<<dim3(BATCH, TOK / 256, 8), 256>>>(out);
}